// round 3
// baseline (speedup 1.0000x reference)
#include <cuda_runtime.h>
#include <math.h>
#include <stdint.h>

#define BHn   64
#define NSEQ  4096
#define DDIM  64
#define MFEAT 256
#define NROWS (BHn * NSEQ)   // 262144

// ---------------- scratch (device globals: sanctioned scratch mechanism) ----
static __device__ float g_ctx[BHn * MFEAT * DDIM];      // context, 4MB
static __device__ float g_ksum[BHn * MFEAT];            // 64KB
static __device__ float g_kmax;                         // global stabilizer

// ---------------- f32x2 packed math helpers --------------------------------
__device__ __forceinline__ unsigned long long pk2(float lo, float hi) {
    unsigned long long r;
    asm("mov.b64 %0, {%1,%2};" : "=l"(r) : "f"(lo), "f"(hi));
    return r;
}
__device__ __forceinline__ void upk2(unsigned long long v, float& lo, float& hi) {
    asm("mov.b64 {%0,%1}, %2;" : "=f"(lo), "=f"(hi) : "l"(v));
}
__device__ __forceinline__ unsigned long long ffma2(unsigned long long a,
                                                    unsigned long long b,
                                                    unsigned long long c) {
    unsigned long long d;
    asm("fma.rn.f32x2 %0, %1, %2, %3;" : "=l"(d) : "l"(a), "l"(b), "l"(c));
    return d;
}

// ---------------- polynomial exp (FMA pipe, avoids MUFU bottleneck) --------
__device__ __forceinline__ float fexp_poly(float x) {
    x = fmaxf(x, -86.0f);                       // exp(-86) ~ 4e-38, safe floor
    float t = x * 1.4426950408889634f;          // x * log2(e)
    float z = t + 12582912.0f;                  // round-to-nearest via magic
    int   i = __float_as_int(z) - 0x4B400000;   // integer part
    float f = t - (z - 12582912.0f);            // frac in [-0.5, 0.5]
    float p = 1.5403530e-4f;                    // 2^f Taylor, deg 6, err ~1e-7
    p = fmaf(p, f, 1.3333558e-3f);
    p = fmaf(p, f, 9.6181291e-3f);
    p = fmaf(p, f, 5.5504109e-2f);
    p = fmaf(p, f, 2.4022651e-1f);
    p = fmaf(p, f, 6.9314718e-1f);
    p = fmaf(p, f, 1.0f);
    return __int_as_float((i + 127) << 23) * p;
}

__device__ __forceinline__ void atomicMaxFloat(float* addr, float val) {
    int* ai = (int*)addr;
    float cur = __int_as_float(*((volatile int*)ai));
    while (val > cur) {
        int assumed = __float_as_int(cur);
        int prev = atomicCAS(ai, assumed, __float_as_int(val));
        if (prev == assumed) break;
        cur = __int_as_float(prev);
    }
}

// ---------------- kernel 0: reset accumulators -----------------------------
__global__ void k_init() {
    unsigned i = blockIdx.x * blockDim.x + threadIdx.x;
    if (i == 0) g_kmax = -3.0e38f;
    const unsigned tot = BHn * MFEAT * DDIM;
    for (unsigned j = i; j < tot; j += gridDim.x * blockDim.x) g_ctx[j] = 0.f;
    if (i < BHn * MFEAT) g_ksum[i] = 0.f;
}

// ---------------- kernel 1: kdash GEMM -> global max only ------------------
__global__ __launch_bounds__(256) void k_kmax(const float* __restrict__ K,
                                              const float* __restrict__ P) {
    extern __shared__ float sm[];
    float* sK   = sm;            // 64 x 68 (padded)          4352
    float* sPt  = sm + 4352;     // 64 x 256 (P transposed)  16384
    float* sred = sm + 20736;    // 8
    const int t = threadIdx.x;
    const size_t rowbase = (size_t)blockIdx.x * 64;

    {   // load K tile (coalesced float4), padded smem
        const float4* gk = (const float4*)(K + rowbase * DDIM);
        #pragma unroll
        for (int i = 0; i < 4; i++) {
            int idx = t + i * 256;
            int r = idx >> 4, c4 = idx & 15;
            *(float4*)&sK[r * 68 + c4 * 4] = gk[r * 16 + c4];
        }
    }
    {   // load P transposed: sPt[kk][m]
        const float* pr = P + (size_t)t * DDIM;
        for (int kk = 0; kk < 64; kk++) sPt[kk * 256 + t] = pr[kk];
    }
    __syncthreads();
    const int ty = t >> 4, cx = t & 15, r0 = ty * 4;
    unsigned long long acc[4][8];
    #pragma unroll
    for (int i = 0; i < 4; i++)
        #pragma unroll
        for (int j = 0; j < 8; j++) acc[i][j] = 0ULL;

    for (int kk = 0; kk < 64; kk += 2) {
        unsigned long long b0[8], b1[8];
        #pragma unroll
        for (int j = 0; j < 8; j++) {
            b0[j] = *(const unsigned long long*)&sPt[kk * 256 + 2 * cx + 32 * j];
            b1[j] = *(const unsigned long long*)&sPt[kk * 256 + 256 + 2 * cx + 32 * j];
        }
        #pragma unroll
        for (int i = 0; i < 4; i++) {
            float2 a2 = *(const float2*)&sK[(r0 + i) * 68 + kk];
            unsigned long long ax = pk2(a2.x, a2.x);
            unsigned long long ay = pk2(a2.y, a2.y);
            #pragma unroll
            for (int j = 0; j < 8; j++) {
                acc[i][j] = ffma2(ax, b0[j], acc[i][j]);
                acc[i][j] = ffma2(ay, b1[j], acc[i][j]);
            }
        }
    }
    float tmax = -3.0e38f;
    #pragma unroll
    for (int i = 0; i < 4; i++)
        #pragma unroll
        for (int j = 0; j < 8; j++) {
            float x, y; upk2(acc[i][j], x, y);
            tmax = fmaxf(tmax, fmaxf(x, y));
        }
    #pragma unroll
    for (int o = 16; o > 0; o >>= 1)
        tmax = fmaxf(tmax, __shfl_xor_sync(0xffffffffu, tmax, o));
    if ((t & 31) == 0) sred[t >> 5] = tmax;
    __syncthreads();
    if (t == 0) {
        float m = sred[0];
        #pragma unroll
        for (int w = 1; w < 8; w++) m = fmaxf(m, sred[w]);
        // max of raw dot; NORM > 0 so apply afterwards
        atomicMaxFloat(&g_kmax, m * 0.35355339059327373f);
    }
}

// ---------------- kernel 2: fused kdash recompute + k' -> context + ksum ---
// grid (2 chunks, 64 heads) = 128 blocks (one wave); chunk = 2048 rows
__global__ __launch_bounds__(256) void k_context(const float* __restrict__ K,
                                                 const float* __restrict__ P,
                                                 const float* __restrict__ V) {
    extern __shared__ float sm[];
    float* sPt = sm;             // 64 x 256 (16384)
    float* sK  = sm + 16384;     // 64 x 68  (4352)
    float* skp = sm + 20736;     // 64 x 256 (16384) k' tile
    float* sv  = sm + 37120;     // 64 x 64  (4096)
    float* sdg = sm + 41216;     // 64
    const int t = threadIdx.x;
    const int bh = blockIdx.y;
    const size_t rowbase = (size_t)bh * NSEQ + (size_t)blockIdx.x * 2048;
    const float stab = g_kmax;
    const float NORM = 0.35355339059327373f;

    {   // load P transposed once
        const float* pr = P + (size_t)t * DDIM;
        for (int kk = 0; kk < 64; kk++) sPt[kk * 256 + t] = pr[kk];
    }
    const int ty = t >> 4, cx = t & 15, r0 = ty * 4;   // GEMM1 mapping
    const int tm = t & 63, te = t >> 6;                // GEMM2 mapping
    const int m0 = tm * 4, e0 = te * 16;

    unsigned long long ctx[4][8];
    #pragma unroll
    for (int i = 0; i < 4; i++)
        #pragma unroll
        for (int j = 0; j < 8; j++) ctx[i][j] = 0ULL;
    float ksl[4] = {0.f, 0.f, 0.f, 0.f};

    for (int s = 0; s < 32; s++) {
        const size_t rb = rowbase + (size_t)s * 64;
        __syncthreads();   // previous-iteration readers done with sK/skp/sv
        {   // stage K + V subtiles (coalesced float4)
            const float4* gk = (const float4*)(K + rb * DDIM);
            const float4* gv = (const float4*)(V + rb * DDIM);
            #pragma unroll
            for (int i = 0; i < 4; i++) {
                int idx = t + i * 256;
                int r = idx >> 4, c4 = idx & 15;
                *(float4*)&sK[r * 68 + c4 * 4] = gk[r * 16 + c4];
                ((float4*)sv)[idx] = gv[idx];
            }
        }
        __syncthreads();
        if (t < 64) {   // diag = sumsq * 0.5 * norm^2 = sumsq/16
            float ssum = 0.f;
            const float* rp = &sK[t * 68];
            #pragma unroll
            for (int kk = 0; kk < 64; kk++) ssum = fmaf(rp[kk], rp[kk], ssum);
            sdg[t] = ssum * 0.0625f;
        }
        // GEMM1: kdash tile
        unsigned long long acc[4][8];
        #pragma unroll
        for (int i = 0; i < 4; i++)
            #pragma unroll
            for (int j = 0; j < 8; j++) acc[i][j] = 0ULL;
        for (int kk = 0; kk < 64; kk += 2) {
            unsigned long long b0[8], b1[8];
            #pragma unroll
            for (int j = 0; j < 8; j++) {
                b0[j] = *(const unsigned long long*)&sPt[kk * 256 + 2 * cx + 32 * j];
                b1[j] = *(const unsigned long long*)&sPt[kk * 256 + 256 + 2 * cx + 32 * j];
            }
            #pragma unroll
            for (int i = 0; i < 4; i++) {
                float2 a2 = *(const float2*)&sK[(r0 + i) * 68 + kk];
                unsigned long long ax = pk2(a2.x, a2.x);
                unsigned long long ay = pk2(a2.y, a2.y);
                #pragma unroll
                for (int j = 0; j < 8; j++) {
                    acc[i][j] = ffma2(ax, b0[j], acc[i][j]);
                    acc[i][j] = ffma2(ay, b1[j], acc[i][j]);
                }
            }
        }
        __syncthreads();   // sdg ready, skp free for rewrite
        #pragma unroll
        for (int i = 0; i < 4; i++) {   // exp epilogue -> skp
            float dg = sdg[r0 + i];
            float* op = &skp[(r0 + i) * 256];
            #pragma unroll
            for (int j = 0; j < 8; j++) {
                float x, y; upk2(acc[i][j], x, y);
                x = 0.0625f * (fexp_poly(fmaf(x, NORM, -dg) - stab) + 1e-4f);
                y = 0.0625f * (fexp_poly(fmaf(y, NORM, -dg) - stab) + 1e-4f);
                *(float2*)&op[2 * cx + 32 * j] = make_float2(x, y);
            }
        }
        __syncthreads();
        // GEMM2: ctx[m0..+3][e0..+15] += k'^T @ V over 64 rows
        for (int r = 0; r < 64; r++) {
            float4 k4 = *(const float4*)&skp[r * 256 + m0];
            if (te == 0) {
                ksl[0] += k4.x; ksl[1] += k4.y; ksl[2] += k4.z; ksl[3] += k4.w;
            }
            unsigned long long a0 = pk2(k4.x, k4.x), a1 = pk2(k4.y, k4.y);
            unsigned long long a2_ = pk2(k4.z, k4.z), a3 = pk2(k4.w, k4.w);
            #pragma unroll
            for (int j = 0; j < 8; j++) {
                unsigned long long v2 =
                    *(const unsigned long long*)&sv[r * 64 + e0 + 2 * j];
                ctx[0][j] = ffma2(a0, v2, ctx[0][j]);
                ctx[1][j] = ffma2(a1, v2, ctx[1][j]);
                ctx[2][j] = ffma2(a2_, v2, ctx[2][j]);
                ctx[3][j] = ffma2(a3, v2, ctx[3][j]);
            }
        }
    }
    if (te == 0) {
        #pragma unroll
        for (int i = 0; i < 4; i++)
            atomicAdd(&g_ksum[bh * MFEAT + m0 + i], ksl[i]);
    }
    #pragma unroll
    for (int i = 0; i < 4; i++) {
        float* cp = &g_ctx[((size_t)bh * MFEAT + m0 + i) * DDIM + e0];
        #pragma unroll
        for (int j = 0; j < 8; j++) {
            float x, y; upk2(ctx[i][j], x, y);
            atomicAdd(&cp[2 * j], x);
            atomicAdd(&cp[2 * j + 1], y);
        }
    }
}

// ---------------- kernel 3: fused q' + output ------------------------------
// per (head, 64-row tile): qdash GEMM -> rowmax -> exp -> q'@ctx + D^-1
__global__ __launch_bounds__(256) void k_final(const float* __restrict__ Q,
                                               const float* __restrict__ P,
                                               float* __restrict__ Out) {
    extern __shared__ float sm[];
    float* sQ    = sm;            // 64 x 68
    float* sPt   = sm + 4352;     // 64 x 256
    float* sctx  = sm + 20736;    // 256 x 64
    float* sqd   = sm + 37120;    // 64 x 256 (qdash -> q')
    float* sksum = sm + 53504;    // 256
    float* sdg   = sm + 53760;    // 64
    float* srmax = sm + 53824;    // 64
    float* sD    = sm + 53888;    // 64
    float* srp   = sm + 53952;    // 64 x 16 partial rowmax
    const int t = threadIdx.x;
    const int bh = blockIdx.y;
    const size_t grow = (size_t)bh * NSEQ + (size_t)blockIdx.x * 64;

    {   // stage Q tile, Pt, context, ksum
        const float4* gq = (const float4*)(Q + grow * DDIM);
        #pragma unroll
        for (int i = 0; i < 4; i++) {
            int idx = t + i * 256;
            int r = idx >> 4, c4 = idx & 15;
            *(float4*)&sQ[r * 68 + c4 * 4] = gq[r * 16 + c4];
        }
        const float* pr = P + (size_t)t * DDIM;
        for (int kk = 0; kk < 64; kk++) sPt[kk * 256 + t] = pr[kk];
        const float4* gc = (const float4*)&g_ctx[(size_t)bh * MFEAT * DDIM];
        #pragma unroll
        for (int i = 0; i < 16; i++)
            ((float4*)sctx)[t + i * 256] = gc[t + i * 256];
        sksum[t] = g_ksum[bh * MFEAT + t];
    }
    __syncthreads();
    if (t < 64) {
        float s = 0.f;
        const float* rp = &sQ[t * 68];
        #pragma unroll
        for (int kk = 0; kk < 64; kk++) s = fmaf(rp[kk], rp[kk], s);
        sdg[t] = s * 0.0625f;
    }
    const int ty = t >> 4, cx = t & 15, r0 = ty * 4;
    {   // GEMM1: qdash = NORM * Q @ Pt
        unsigned long long acc[4][8];
        #pragma unroll
        for (int i = 0; i < 4; i++)
            #pragma unroll
            for (int j = 0; j < 8; j++) acc[i][j] = 0ULL;
        for (int kk = 0; kk < 64; kk += 2) {
            unsigned long long b0[8], b1[8];
            #pragma unroll
            for (int j = 0; j < 8; j++) {
                b0[j] = *(const unsigned long long*)&sPt[kk * 256 + 2 * cx + 32 * j];
                b1[j] = *(const unsigned long long*)&sPt[kk * 256 + 256 + 2 * cx + 32 * j];
            }
            #pragma unroll
            for (int i = 0; i < 4; i++) {
                float2 a2 = *(const float2*)&sQ[(r0 + i) * 68 + kk];
                unsigned long long ax = pk2(a2.x, a2.x);
                unsigned long long ay = pk2(a2.y, a2.y);
                #pragma unroll
                for (int j = 0; j < 8; j++) {
                    acc[i][j] = ffma2(ax, b0[j], acc[i][j]);
                    acc[i][j] = ffma2(ay, b1[j], acc[i][j]);
                }
            }
        }
        const float NORM = 0.35355339059327373f;
        #pragma unroll
        for (int i = 0; i < 4; i++) {
            float pm = -3.0e38f;
            float* rp2 = &sqd[(r0 + i) * 256];
            #pragma unroll
            for (int j = 0; j < 8; j++) {
                float x, y; upk2(acc[i][j], x, y);
                x *= NORM; y *= NORM;
                pm = fmaxf(pm, fmaxf(x, y));
                *(float2*)&rp2[2 * cx + 32 * j] = make_float2(x, y);
            }
            srp[(r0 + i) * 16 + cx] = pm;
        }
    }
    __syncthreads();
    if (t < 64) {
        float m = srp[t * 16];
        #pragma unroll
        for (int j = 1; j < 16; j++) m = fmaxf(m, srp[t * 16 + j]);
        srmax[t] = m;
    }
    __syncthreads();
    for (int r = 0; r < 64; r++) {   // exp phase: dash -> q' (coalesced smem)
        float val = sqd[r * 256 + t];
        float qp = 0.0625f * (fexp_poly(val - sdg[r] - srmax[r]) + 1e-4f);
        sqd[r * 256 + t] = qp;
    }
    __syncthreads();
    {   // GEMM2: out = q' @ ctx (+ D = q'·ksum on cx==0)
        unsigned long long acc[4][2];
        #pragma unroll
        for (int i = 0; i < 4; i++) { acc[i][0] = 0ULL; acc[i][1] = 0ULL; }
        float dac[4] = {0.f, 0.f, 0.f, 0.f};
        for (int kk = 0; kk < 256; kk += 2) {
            unsigned long long b00 = *(const unsigned long long*)&sctx[kk * 64 + 2 * cx];
            unsigned long long b01 = *(const unsigned long long*)&sctx[kk * 64 + 2 * cx + 32];
            unsigned long long b10 = *(const unsigned long long*)&sctx[kk * 64 + 64 + 2 * cx];
            unsigned long long b11 = *(const unsigned long long*)&sctx[kk * 64 + 64 + 2 * cx + 32];
            float ks0 = sksum[kk], ks1 = sksum[kk + 1];
            #pragma unroll
            for (int i = 0; i < 4; i++) {
                float2 a2 = *(const float2*)&sqd[(r0 + i) * 256 + kk];
                unsigned long long ax = pk2(a2.x, a2.x);
                unsigned long long ay = pk2(a2.y, a2.y);
                acc[i][0] = ffma2(ax, b00, acc[i][0]);
                acc[i][0] = ffma2(ay, b10, acc[i][0]);
                acc[i][1] = ffma2(ax, b01, acc[i][1]);
                acc[i][1] = ffma2(ay, b11, acc[i][1]);
                if (cx == 0) dac[i] = fmaf(a2.x, ks0, fmaf(a2.y, ks1, dac[i]));
            }
        }
        if (cx == 0) {
            #pragma unroll
            for (int i = 0; i < 4; i++) sD[r0 + i] = dac[i];
        }
        __syncthreads();
        #pragma unroll
        for (int i = 0; i < 4; i++) {
            float dinv = 1.0f / sD[r0 + i];
            float* op = Out + (grow + r0 + i) * DDIM;
            #pragma unroll
            for (int j = 0; j < 2; j++) {
                float x, y; upk2(acc[i][j], x, y);
                *(float2*)&op[2 * cx + 32 * j] = make_float2(x * dinv, y * dinv);
            }
        }
    }
}

// ---------------- host launcher --------------------------------------------
extern "C" void kernel_launch(void* const* d_in, const int* in_sizes, int n_in,
                              void* d_out, int out_size) {
    const float* q = (const float*)d_in[0];
    const float* k = (const float*)d_in[1];
    const float* v = (const float*)d_in[2];
    const float* P = (const float*)d_in[3];
    float* out = (float*)d_out;
    (void)in_sizes; (void)n_in; (void)out_size;

    cudaFuncSetAttribute(k_kmax, cudaFuncAttributeMaxDynamicSharedMemorySize, 83232);
    cudaFuncSetAttribute(k_context, cudaFuncAttributeMaxDynamicSharedMemorySize, 165120);
    cudaFuncSetAttribute(k_final, cudaFuncAttributeMaxDynamicSharedMemorySize, 219904);

    k_init<<<2048, 256>>>();
    k_kmax<<<NROWS / 64, 256, 83232>>>(k, P);
    k_context<<<dim3(2, BHn), 256, 165120>>>(k, P, v);
    k_final<<<dim3(NSEQ / 64, BHn), 256, 219904>>>(q, P, out);
}